// round 1
// baseline (speedup 1.0000x reference)
#include <cuda_runtime.h>

// YeoJohnson_62053687493093
// x: [4096, 16384] fp32, lmbda: [16384] fp32 (per-column), out: [4096, 16384] fp32
//
// out = pos ? ((x+1)^lm - 1)/lm              (lm==0 -> log1p(x))
//           : -(((1-x)^(2-lm)) - 1)/(2-lm)   (lm==2 -> -log1p(-x); unreachable for lm in [0,1))
//
// Strategy: HBM-bound streaming kernel. 2 MUFU (lg2+ex2) per element; the
// divide is replaced by a multiply with per-column reciprocals precomputed by
// a prep kernel into __device__ tables (keeps MUFU at 2/elem so DRAM stays
// the binding resource).

#define YJ_D   16384
#define YJ_D4  (YJ_D / 4)

// Per-column reciprocal tables (16-byte aligned for float4 access).
__device__ __align__(16) float g_rl[YJ_D];   // 1/lm        (1 if lm == 0)
__device__ __align__(16) float g_r2[YJ_D];   // 1/(2 - lm)  (1 if lm == 2)

__global__ void yj_prep_kernel(const float* __restrict__ lmbda) {
    int i = blockIdx.x * blockDim.x + threadIdx.x;
    if (i < YJ_D) {
        float lm = lmbda[i];
        g_rl[i] = (lm == 0.0f) ? 1.0f : 1.0f / lm;
        float tm = 2.0f - lm;
        g_r2[i] = (tm == 0.0f) ? 1.0f : 1.0f / tm;
    }
}

__device__ __forceinline__ float fast_lg2(float v) {
    float r;
    asm("lg2.approx.f32 %0, %1;" : "=f"(r) : "f"(v));
    return r;
}
__device__ __forceinline__ float fast_ex2(float t) {
    float r;
    asm("ex2.approx.f32 %0, %1;" : "=f"(r) : "f"(t));
    return r;
}

__device__ __forceinline__ float yj_one(float x, float lm, float rl, float r2) {
    bool pos = (x >= 0.0f);
    float v   = pos ? (x + 1.0f) : (1.0f - x);   // >= 1
    float e   = pos ? lm         : (2.0f - lm);
    float rcp = pos ? rl         : r2;

    if (e == 0.0f) {
        // only reachable when pos && lm == 0 (lm in [0,1))
        return log1pf(x);
    }
    float t = e * fast_lg2(v);
    float p = fast_ex2(t);
    float r = (p - 1.0f) * rcp;
    return pos ? r : -r;
}

__global__ void __launch_bounds__(256)
yj_kernel(const float4* __restrict__ x,
          const float4* __restrict__ lam4,
          float4* __restrict__ out,
          int n4) {
    int i = blockIdx.x * blockDim.x + threadIdx.x;
    if (i >= n4) return;

    int c = i & (YJ_D4 - 1);   // float4 column index within a row

    float4 xv = x[i];
    float4 lv = lam4[c];
    float4 rl = reinterpret_cast<const float4*>(g_rl)[c];
    float4 r2 = reinterpret_cast<const float4*>(g_r2)[c];

    float4 o;
    o.x = yj_one(xv.x, lv.x, rl.x, r2.x);
    o.y = yj_one(xv.y, lv.y, rl.y, r2.y);
    o.z = yj_one(xv.z, lv.z, rl.z, r2.z);
    o.w = yj_one(xv.w, lv.w, rl.w, r2.w);
    out[i] = o;
}

extern "C" void kernel_launch(void* const* d_in, const int* in_sizes, int n_in,
                              void* d_out, int out_size) {
    const float* x     = (const float*)d_in[0];
    const float* lmbda = (const float*)d_in[1];
    float*       out   = (float*)d_out;

    // Prep: per-column reciprocals (tiny, amortized by L2 residency).
    yj_prep_kernel<<<(YJ_D + 255) / 256, 256>>>(lmbda);

    int n4 = out_size / 4;   // 4096*16384/4 = 16,777,216 float4s
    int threads = 256;
    int blocks  = (n4 + threads - 1) / threads;   // 65536
    yj_kernel<<<blocks, threads>>>(
        (const float4*)x, (const float4*)lmbda, (float4*)out, n4);
}

// round 3
// speedup vs baseline: 1.1195x; 1.1195x over previous
#include <cuda_runtime.h>

// YeoJohnson_62053687493093 — R3 (R2 re-bench after infra failure, + cache hints)
// x: [4096, 16384] fp32, lmbda: [16384] fp32 per-column, out fp32.
//
//  - Row reuse: each thread handles 4 columns x 8 rows. Table loads (lm, 1/lm,
//    1/(2-lm)) amortize 8x; per-thread DRAM MLP goes 1 -> 8 (front-batched).
//  - Branch-free per-element math: v = 1+|x|, fused (p-1)*rcp via FFMA,
//    e==0 limit handled by a select to L*ln2 (no log1pf, no divergent branch),
//    sign restored with a negating select.
//  - Cache policy: streaming (.cs) loads/stores for x/out (zero reuse),
//    __ldg for the per-column tables (high reuse across CTAs).

#define YJ_D    16384
#define YJ_D4   4096          // float4 columns per row
#define YJ_R    8             // rows per thread

__device__ __align__(16) float g_rl[YJ_D];   // 1/lm        (1 if lm == 0)
__device__ __align__(16) float g_r2[YJ_D];   // 1/(2 - lm)  (1 if lm == 2)

__global__ void yj_prep_kernel(const float* __restrict__ lmbda) {
    int i = blockIdx.x * blockDim.x + threadIdx.x;
    if (i < YJ_D) {
        float lm = lmbda[i];
        g_rl[i] = (lm == 0.0f) ? 1.0f : 1.0f / lm;
        float tm = 2.0f - lm;
        g_r2[i] = (tm == 0.0f) ? 1.0f : 1.0f / tm;
    }
}

__device__ __forceinline__ float fast_lg2(float v) {
    float r;
    asm("lg2.approx.f32 %0, %1;" : "=f"(r) : "f"(v));
    return r;
}
__device__ __forceinline__ float fast_ex2(float t) {
    float r;
    asm("ex2.approx.f32 %0, %1;" : "=f"(r) : "f"(t));
    return r;
}

// Branch-free Yeo-Johnson for one element.
// lm: lambda, tm: 2-lm, rl: 1/lm, r2: 1/(2-lm)
__device__ __forceinline__ float yj_one(float x, float lm, float tm,
                                        float rl, float r2) {
    bool  pos = (x >= 0.0f);
    float v   = 1.0f + fabsf(x);            // FADD with |.| modifier, v >= 1
    float L   = fast_lg2(v);                // MUFU
    float e   = pos ? lm : tm;              // FSEL
    float rcp = pos ? rl : r2;              // FSEL
    float p   = fast_ex2(e * L);            // FMUL + MUFU
    float r   = fmaf(p, rcp, -rcp);         // (p-1)*rcp, one FFMA
    // e -> 0 limit: (2^(e*L)-1)/e -> L*ln2  (covers lm==0 and lm==2 exactly)
    float lim = L * 0.69314718056f;         // FMUL
    r = (e == 0.0f) ? lim : r;              // FSETP + FSEL
    return pos ? r : -r;                    // FSEL with negate
}

__global__ void __launch_bounds__(256)
yj_kernel(const float4* __restrict__ x,
          const float4* __restrict__ lam4,
          float4* __restrict__ out) {
    int c4   = blockIdx.x * blockDim.x + threadIdx.x;   // 0..YJ_D4-1
    int row0 = blockIdx.y * YJ_R;

    // Per-column parameters, loaded once, reused for YJ_R rows (L2-resident).
    float4 lv = __ldg(&lam4[c4]);
    float4 rl = __ldg(&reinterpret_cast<const float4*>(g_rl)[c4]);
    float4 r2 = __ldg(&reinterpret_cast<const float4*>(g_r2)[c4]);
    float4 tm;
    tm.x = 2.0f - lv.x; tm.y = 2.0f - lv.y;
    tm.z = 2.0f - lv.z; tm.w = 2.0f - lv.w;

    size_t base = (size_t)row0 * YJ_D4 + (size_t)c4;

    // Front-batched streaming DRAM loads: 8 independent LDG.128 in flight.
    float4 xv[YJ_R];
#pragma unroll
    for (int r = 0; r < YJ_R; r++)
        xv[r] = __ldcs(&x[base + (size_t)r * YJ_D4]);

#pragma unroll
    for (int r = 0; r < YJ_R; r++) {
        float4 o;
        o.x = yj_one(xv[r].x, lv.x, tm.x, rl.x, r2.x);
        o.y = yj_one(xv[r].y, lv.y, tm.y, rl.y, r2.y);
        o.z = yj_one(xv[r].z, lv.z, tm.z, rl.z, r2.z);
        o.w = yj_one(xv[r].w, lv.w, tm.w, rl.w, r2.w);
        __stcs(&out[base + (size_t)r * YJ_D4], o);
    }
}

extern "C" void kernel_launch(void* const* d_in, const int* in_sizes, int n_in,
                              void* d_out, int out_size) {
    const float* x     = (const float*)d_in[0];
    const float* lmbda = (const float*)d_in[1];
    float*       out   = (float*)d_out;

    yj_prep_kernel<<<(YJ_D + 255) / 256, 256>>>(lmbda);

    int rows = out_size / YJ_D;                 // 4096
    dim3 block(256);
    dim3 grid(YJ_D4 / 256, rows / YJ_R);        // (16, 512) = 8192 blocks
    yj_kernel<<<grid, block>>>(
        (const float4*)x, (const float4*)lmbda, (float4*)out);
}